// round 12
// baseline (speedup 1.0000x reference)
#include <cuda_runtime.h>
#include <cstdint>

#define NB      2
#define SEQ     2048
#define DMODEL  1024
#define HEADS   16
#define HD      64
#define MTOT    (NB*SEQ)        // 4096
#define N_QKV   (3*DMODEL)      // 3072

// Scratch (static device globals -- no allocation anywhere)
__device__ float g_qb[NB*HEADS*SEQ*HD];   // [b,h,s,hd]  (tf32-rounded)
__device__ float g_kb[NB*HEADS*SEQ*HD];
__device__ float g_vb[NB*HEADS*SEQ*HD];
__device__ float g_ab[MTOT*DMODEL];       // attention out (tf32-rounded)
__device__ float g_xr[MTOT*DMODEL];       // tf32-rounded x
__device__ float g_wqr[N_QKV*DMODEL];     // tf32-rounded Wqkv
__device__ float g_wdr[DMODEL*DMODEL];    // tf32-rounded Wd

// ---------------- helpers ----------------
__device__ __forceinline__ unsigned f2tf(float x) {
    unsigned u; asm("cvt.rna.tf32.f32 %0, %1;" : "=r"(u) : "f"(x)); return u;
}
__device__ __forceinline__ float f2tff(float x) { return __uint_as_float(f2tf(x)); }

__device__ __forceinline__ void mma8(float c[4],
                                     unsigned a0, unsigned a1, unsigned a2, unsigned a3,
                                     unsigned b0, unsigned b1) {
    asm volatile(
        "mma.sync.aligned.m16n8k8.row.col.f32.tf32.tf32.f32 "
        "{%0,%1,%2,%3}, {%4,%5,%6,%7}, {%8,%9}, {%0,%1,%2,%3};\n"
        : "+f"(c[0]), "+f"(c[1]), "+f"(c[2]), "+f"(c[3])
        : "r"(a0), "r"(a1), "r"(a2), "r"(a3), "r"(b0), "r"(b1));
}

__device__ __forceinline__ uint32_t s2u(const void* p) {
    uint32_t a;
    asm("{ .reg .u64 t; cvta.to.shared.u64 t, %1; cvt.u32.u64 %0, t; }"
        : "=r"(a) : "l"(p));
    return a;
}

__device__ __forceinline__ void cpasync16(uint32_t s, const void* g) {
    asm volatile("cp.async.cg.shared.global [%0], [%1], 16;" :: "r"(s), "l"(g));
}
__device__ __forceinline__ void cpcommit() {
    asm volatile("cp.async.commit_group;" ::: "memory");
}
__device__ __forceinline__ void cpwait0() {
    asm volatile("cp.async.wait_group 0;" ::: "memory");
}
__device__ __forceinline__ void cpwait1() {
    asm volatile("cp.async.wait_group 1;" ::: "memory");
}
__device__ __forceinline__ void cpwait2() {
    asm volatile("cp.async.wait_group 2;" ::: "memory");
}

// ---------------- pre-round: rna-round x, Wqkv, Wd to tf32-in-fp32 ----------------
__global__ void round_kernel(const float* __restrict__ x,
                             const float* __restrict__ wqkv,
                             const float* __restrict__ wd)
{
    const int N1 = MTOT * DMODEL / 4;
    const int N2 = N_QKV * DMODEL / 4;
    const int N3 = DMODEL * DMODEL / 4;
    const int total = N1 + N2 + N3;
    for (int i = blockIdx.x * blockDim.x + threadIdx.x; i < total;
         i += gridDim.x * blockDim.x) {
        const float4* src; float4* dst; int off;
        if (i < N1)           { src = (const float4*)x;    dst = (float4*)g_xr;  off = i; }
        else if (i < N1 + N2) { src = (const float4*)wqkv; dst = (float4*)g_wqr; off = i - N1; }
        else                  { src = (const float4*)wd;   dst = (float4*)g_wdr; off = i - N1 - N2; }
        float4 v = src[off];
        v.x = f2tff(v.x); v.y = f2tff(v.y); v.z = f2tff(v.z); v.w = f2tff(v.w);
        dst[off] = v;
    }
}

// ---------------- GEMM: C[M,N] = A[M,K] @ B[N,K]^T + bias ----------------
// Pre-rounded inputs; cp.async 3-stage pipeline; unpadded 128B rows with a
// parity swizzle col4' = col4 ^ (4*(row&1)) so dual-mma float4 fragment loads
// are conflict-free LDS.128. k-mapping inside each 16-col block: mma j
// (j=0,1) slot t <-> col 4t+2j, slot t+4 <-> col 4t+2j+1 (A and B agree; the
// two mmas partition k, so the C tile/accumulators are unchanged).
#define GEMM_STAGE_BYTES 32768                 // (A+B) x 128 rows x 128B
#define GEMM_SMEM_BYTES (3 * GEMM_STAGE_BYTES) // 98304, 2 CTAs/SM fits

template<int MODE>
__global__ __launch_bounds__(256, 2)
void gemm_kernel(const float* __restrict__ Bw, const float* __restrict__ bias,
                 float* __restrict__ C, int M, int N, int K)
{
    extern __shared__ float gsm[];
    const float* A = (MODE == 1) ? g_ab : g_xr;
    const float* B = Bw;

    const uint32_t sbase = s2u(gsm);
    const int tid  = threadIdx.x;
    const int wid  = tid >> 5, lane = tid & 31;
    const int g    = lane >> 2, t = lane & 3;
    const int wm   = (wid >> 2) * 64;   // 2 warps in m
    const int wn   = (wid & 3) * 32;    // 4 warps in n
    const int m0   = blockIdx.y * 128, n0 = blockIdx.x * 128;

    // staging: 4 (row,col4) pairs per thread; swizzled dest byte offsets
    int srow[4], scol4[4]; uint32_t sdst[4];
#pragma unroll
    for (int i = 0; i < 4; i++) {
        int lin = tid + i * 256;
        srow[i]  = lin >> 3;
        scol4[i] = lin & 7;
        sdst[i]  = (uint32_t)(srow[i] * 128) + (uint32_t)((scol4[i] ^ (4 * (srow[i] & 1))) << 4);
    }

    float acc[4][4][4];
#pragma unroll
    for (int i = 0; i < 4; i++)
#pragma unroll
        for (int j = 0; j < 4; j++)
#pragma unroll
            for (int c = 0; c < 4; c++) acc[i][j][c] = 0.f;

    const int NCH = K / 32;

    // issue chunk ch into stage st
    auto issue = [&](int ch, int st) {
        const int k0 = ch * 32;
        const uint32_t sb = sbase + (uint32_t)st * GEMM_STAGE_BYTES;
#pragma unroll
        for (int i = 0; i < 4; i++) {
            cpasync16(sb + sdst[i],
                      &A[(size_t)(m0 + srow[i]) * K + k0 + scol4[i] * 4]);
            cpasync16(sb + 16384u + sdst[i],
                      &B[(size_t)(n0 + srow[i]) * K + k0 + scol4[i] * 4]);
        }
        cpcommit();
    };

    issue(0, 0);
    if (NCH > 1) issue(1, 1);

    for (int ch = 0; ch < NCH; ch++) {
        if (ch + 2 < NCH) { issue(ch + 2, (ch + 2) % 3); cpwait2(); }
        else if (ch + 1 < NCH) { cpwait1(); }
        else { cpwait0(); }
        __syncthreads();

        const char* As = (const char*)gsm + (ch % 3) * GEMM_STAGE_BYTES;
        const char* Bs = As + 16384;

#pragma unroll
        for (int kk = 0; kk < 2; kk++) {       // 16-col block index
            // B fragments: one float4 per nf feeds both mmas
            float4 bv[4];
#pragma unroll
            for (int nf = 0; nf < 4; nf++) {
                int rn = wn + nf * 8 + g;
                bv[nf] = *reinterpret_cast<const float4*>(
                    Bs + rn * 128 + (((kk * 4 + t) ^ (4 * (rn & 1))) << 4));
            }
#pragma unroll
            for (int mf = 0; mf < 4; mf++) {
                int r0 = wm + mf * 16 + g, r1 = r0 + 8;
                float4 a0v = *reinterpret_cast<const float4*>(
                    As + r0 * 128 + (((kk * 4 + t) ^ (4 * (r0 & 1))) << 4));
                float4 a1v = *reinterpret_cast<const float4*>(
                    As + r1 * 128 + (((kk * 4 + t) ^ (4 * (r1 & 1))) << 4));
#pragma unroll
                for (int nf = 0; nf < 4; nf++) {
                    mma8(acc[mf][nf],
                         __float_as_uint(a0v.x), __float_as_uint(a1v.x),
                         __float_as_uint(a0v.y), __float_as_uint(a1v.y),
                         __float_as_uint(bv[nf].x), __float_as_uint(bv[nf].y));
                    mma8(acc[mf][nf],
                         __float_as_uint(a0v.z), __float_as_uint(a1v.z),
                         __float_as_uint(a0v.w), __float_as_uint(a1v.w),
                         __float_as_uint(bv[nf].z), __float_as_uint(bv[nf].w));
                }
            }
        }
        __syncthreads();   // stage (ch%3) free before iter ch+1 overwrites it
    }

#pragma unroll
    for (int mf = 0; mf < 4; mf++)
#pragma unroll
        for (int nf = 0; nf < 4; nf++)
#pragma unroll
            for (int c = 0; c < 4; c++) {
                int row = m0 + wm + mf * 16 + g + ((c >= 2) ? 8 : 0);
                int col = n0 + wn + nf * 8 + 2 * t + (c & 1);
                float v = acc[mf][nf][c] + bias[col];
                if (MODE == 0) {
                    int part = col >> 10, nn = col & 1023;
                    int hh = nn >> 6, e = nn & 63;
                    int bb = row >> 11, sq = row & 2047;
                    float* dst = (part == 0) ? g_qb : ((part == 1) ? g_kb : g_vb);
                    dst[(((size_t)(bb * HEADS + hh)) * SEQ + sq) * HD + e] = f2tff(v);
                } else {
                    C[(size_t)row * N + col] = v;
                }
            }
}

// ---------------- Flash attention (unchanged from R10 winner) ----------------
// 256 threads (8 warps), 128-row q tile (16 tiles). CTA x=p handles tiles
// {p, 15-p}: causal work is a uniform 34 kv-iterations per CTA.
// K/V double-buffered cp.async, stride 72. P separate, rounded at store.
#define FA_SMEM_BYTES ((2*64*72 + 2*64*72 + 128*68) * 4)   // 108544

__global__ __launch_bounds__(256)
void fa_kernel(const int* __restrict__ maskp)
{
    extern __shared__ float fsm[];
    // float offsets: K stage s: s*4608; V stage s: 9216 + s*4608; P: 18432
    float* Ps = fsm + 18432;

    const int tid = threadIdx.x, wid = tid >> 5, lane = tid & 31;
    const int g = lane >> 2, t = lane & 3;
    const int bh = blockIdx.y;
    const int causal = (maskp[0] != 0);

    const float* kp = g_kb + (size_t)bh * SEQ * HD;
    const float* vp = g_vb + (size_t)bh * SEQ * HD;
    const uint32_t fbase = s2u(fsm);
    const int wr = wid * 16;
    const int row0 = wr + g, row1 = wr + g + 8;
    const int b = bh >> 4, h = bh & 15;

    int krow[4], kc4[4];
#pragma unroll
    for (int i = 0; i < 4; i++) {
        int lin = tid + i * 256;
        krow[i] = lin >> 4;
        kc4[i]  = (lin & 15) << 2;
    }

    for (int sub = 0; sub < 2; sub++) {
        const int Q = sub ? (15 - (int)blockIdx.x) : (int)blockIdx.x;
        const float* qp = g_qb + ((size_t)bh * SEQ + Q * 128) * HD;

        unsigned qf[8][4];
#pragma unroll
        for (int kk = 0; kk < 8; kk++) {
            float2 x0 = *reinterpret_cast<const float2*>(&qp[(size_t)row0 * HD + kk * 8 + 2 * t]);
            float2 x1 = *reinterpret_cast<const float2*>(&qp[(size_t)row1 * HD + kk * 8 + 2 * t]);
            qf[kk][0] = __float_as_uint(x0.x);
            qf[kk][1] = __float_as_uint(x1.x);
            qf[kk][2] = __float_as_uint(x0.y);
            qf[kk][3] = __float_as_uint(x1.y);
        }

        float of[8][4];
#pragma unroll
        for (int nf = 0; nf < 8; nf++)
#pragma unroll
            for (int c = 0; c < 4; c++) of[nf][c] = 0.f;

        float m0 = -1e30f, m1 = -1e30f, l0 = 0.f, l1 = 0.f;
        const int grow0 = Q * 128 + row0, grow1 = Q * 128 + row1;

        const int jend = causal ? (2 * Q + 2) : (SEQ / 64);

#pragma unroll
        for (int i = 0; i < 4; i++) {
            uint32_t so = (uint32_t)(krow[i] * 72 + kc4[i]) * 4;
            cpasync16(fbase + so,           &kp[(size_t)krow[i] * HD + kc4[i]]);
            cpasync16(fbase + 36864u + so,  &vp[(size_t)krow[i] * HD + kc4[i]]);
        }
        cpcommit();

        for (int j = 0; j < jend; j++) {
            const int cur = j & 1;
            if (j + 1 < jend) {
                const int nxt = cur ^ 1;
#pragma unroll
                for (int i = 0; i < 4; i++) {
                    uint32_t so = (uint32_t)(nxt * 18432) + (uint32_t)(krow[i] * 72 + kc4[i]) * 4;
                    cpasync16(fbase + so,          &kp[((size_t)(j + 1) * 64 + krow[i]) * HD + kc4[i]]);
                    cpasync16(fbase + 36864u + so, &vp[((size_t)(j + 1) * 64 + krow[i]) * HD + kc4[i]]);
                }
                cpcommit();
                cpwait1();
            } else {
                cpwait0();
            }
            __syncthreads();

            const float* Ks = fsm + cur * 4608;
            const float* Vs = fsm + 9216 + cur * 4608;

            float sf[8][4];
#pragma unroll
            for (int nf = 0; nf < 8; nf++)
#pragma unroll
                for (int c = 0; c < 4; c++) sf[nf][c] = 0.f;
#pragma unroll
            for (int kk = 0; kk < 8; kk++) {
#pragma unroll
                for (int nf = 0; nf < 8; nf++) {
                    float2 bv = *reinterpret_cast<const float2*>(&Ks[(nf * 8 + g) * 72 + kk * 8 + 2 * t]);
                    mma8(sf[nf], qf[kk][0], qf[kk][1], qf[kk][2], qf[kk][3],
                         __float_as_uint(bv.x), __float_as_uint(bv.y));
                }
            }

            const bool mk = causal && (j >= 2 * Q);
            const int jc = j * 64;
#pragma unroll
            for (int nf = 0; nf < 8; nf++) {
                int c0 = jc + nf * 8 + 2 * t, c1 = c0 + 1;
                sf[nf][0] = (mk && c0 > grow0) ? -1e30f : sf[nf][0] * 0.125f;
                sf[nf][1] = (mk && c1 > grow0) ? -1e30f : sf[nf][1] * 0.125f;
                sf[nf][2] = (mk && c0 > grow1) ? -1e30f : sf[nf][2] * 0.125f;
                sf[nf][3] = (mk && c1 > grow1) ? -1e30f : sf[nf][3] * 0.125f;
            }

            float mx0 = -1e30f, mx1 = -1e30f;
#pragma unroll
            for (int nf = 0; nf < 8; nf++) {
                mx0 = fmaxf(mx0, fmaxf(sf[nf][0], sf[nf][1]));
                mx1 = fmaxf(mx1, fmaxf(sf[nf][2], sf[nf][3]));
            }
            mx0 = fmaxf(mx0, __shfl_xor_sync(0xffffffffu, mx0, 1));
            mx0 = fmaxf(mx0, __shfl_xor_sync(0xffffffffu, mx0, 2));
            mx1 = fmaxf(mx1, __shfl_xor_sync(0xffffffffu, mx1, 1));
            mx1 = fmaxf(mx1, __shfl_xor_sync(0xffffffffu, mx1, 2));
            const float nm0 = fmaxf(m0, mx0), nm1 = fmaxf(m1, mx1);

            float sum0 = 0.f, sum1 = 0.f;
#pragma unroll
            for (int nf = 0; nf < 8; nf++) {
                sf[nf][0] = __expf(sf[nf][0] - nm0);
                sf[nf][1] = __expf(sf[nf][1] - nm0);
                sf[nf][2] = __expf(sf[nf][2] - nm1);
                sf[nf][3] = __expf(sf[nf][3] - nm1);
                sum0 += sf[nf][0] + sf[nf][1];
                sum1 += sf[nf][2] + sf[nf][3];
            }
            sum0 += __shfl_xor_sync(0xffffffffu, sum0, 1);
            sum0 += __shfl_xor_sync(0xffffffffu, sum0, 2);
            sum1 += __shfl_xor_sync(0xffffffffu, sum1, 1);
            sum1 += __shfl_xor_sync(0xffffffffu, sum1, 2);

            const float sc0 = __expf(m0 - nm0), sc1 = __expf(m1 - nm1);
            l0 = l0 * sc0 + sum0; l1 = l1 * sc1 + sum1;
            m0 = nm0; m1 = nm1;

#pragma unroll
            for (int nf = 0; nf < 8; nf++) {
                int c0 = nf * 8 + 2 * t;
                Ps[row0 * 68 + c0    ] = f2tff(sf[nf][0]);
                Ps[row0 * 68 + c0 + 1] = f2tff(sf[nf][1]);
                Ps[row1 * 68 + c0    ] = f2tff(sf[nf][2]);
                Ps[row1 * 68 + c0 + 1] = f2tff(sf[nf][3]);
            }
            __syncwarp();

#pragma unroll
            for (int nf = 0; nf < 8; nf++) {
                of[nf][0] *= sc0; of[nf][1] *= sc0; of[nf][2] *= sc1; of[nf][3] *= sc1;
            }
#pragma unroll
            for (int kk = 0; kk < 8; kk++) {
                unsigned a0 = __float_as_uint(Ps[row0 * 68 + kk * 8 + t    ]);
                unsigned a1 = __float_as_uint(Ps[row1 * 68 + kk * 8 + t    ]);
                unsigned a2 = __float_as_uint(Ps[row0 * 68 + kk * 8 + t + 4]);
                unsigned a3 = __float_as_uint(Ps[row1 * 68 + kk * 8 + t + 4]);
#pragma unroll
                for (int nf = 0; nf < 8; nf++) {
                    unsigned b0 = __float_as_uint(Vs[(kk * 8 + t    ) * 72 + nf * 8 + g]);
                    unsigned b1 = __float_as_uint(Vs[(kk * 8 + t + 4) * 72 + nf * 8 + g]);
                    mma8(of[nf], a0, a1, a2, a3, b0, b1);
                }
            }
            __syncthreads();
        }

        const float il0 = 1.f / l0, il1 = 1.f / l1;
        const int sq0 = Q * 128 + row0, sq1 = Q * 128 + row1;
#pragma unroll
        for (int nf = 0; nf < 8; nf++) {
            int col = nf * 8 + 2 * t;
            float2 v0; v0.x = f2tff(of[nf][0] * il0); v0.y = f2tff(of[nf][1] * il0);
            float2 v1; v1.x = f2tff(of[nf][2] * il1); v1.y = f2tff(of[nf][3] * il1);
            *reinterpret_cast<float2*>(&g_ab[(((size_t)b * SEQ + sq0) * HEADS + h) * HD + col]) = v0;
            *reinterpret_cast<float2*>(&g_ab[(((size_t)b * SEQ + sq1) * HEADS + h) * HD + col]) = v1;
        }
    }
}

// ---------------- launch ----------------
extern "C" void kernel_launch(void* const* d_in, const int* in_sizes, int n_in,
                              void* d_out, int out_size)
{
    const float* x    = (const float*)d_in[0];
    const float* Wqkv = (const float*)d_in[1];
    const float* bqkv = (const float*)d_in[2];
    const float* Wd   = (const float*)d_in[3];
    const float* bd   = (const float*)d_in[4];
    const int*   mask = (const int*)d_in[5];
    float* out = (float*)d_out;

    cudaFuncSetAttribute(gemm_kernel<0>, cudaFuncAttributeMaxDynamicSharedMemorySize, GEMM_SMEM_BYTES);
    cudaFuncSetAttribute(gemm_kernel<1>, cudaFuncAttributeMaxDynamicSharedMemorySize, GEMM_SMEM_BYTES);
    cudaFuncSetAttribute(fa_kernel,      cudaFuncAttributeMaxDynamicSharedMemorySize, FA_SMEM_BYTES);

    static float* wq_dev = nullptr;
    static float* wd_dev = nullptr;
    if (!wq_dev) {
        cudaGetSymbolAddress((void**)&wq_dev, g_wqr);
        cudaGetSymbolAddress((void**)&wd_dev, g_wdr);
    }

    round_kernel<<<1024, 256>>>(x, Wqkv, Wd);

    gemm_kernel<0><<<dim3(N_QKV / 128, MTOT / 128), 256, GEMM_SMEM_BYTES>>>(
        wq_dev, bqkv, nullptr, MTOT, N_QKV, DMODEL);

    fa_kernel<<<dim3(8, NB * HEADS), 256, FA_SMEM_BYTES>>>(mask);

    gemm_kernel<1><<<dim3(DMODEL / 128, MTOT / 128), 256, GEMM_SMEM_BYTES>>>(
        wd_dev, bd, out, MTOT, DMODEL, DMODEL);
}